// round 4
// baseline (speedup 1.0000x reference)
#include <cuda_runtime.h>

// AttentionFusion: fused = sigmoid((x1-x2)@w) * x1 + (1-sigmoid(...)) * x2
// N = 16384 rows, D = 2048 cols, fp32. Pure HBM streamer (402 MB min traffic).
//
// R3: multi-row CTA (8 rows) with software double-buffering:
//  - loads for row r+1 issue before the reduce/barrier of row r stalls the warp
//  - w held in registers for the whole CTA (loaded once, not 16384x from L2)
//  - __ldcs / __stcs streaming hints (data touched exactly once)
// Grid 2048 CTAs -> ~3.5 waves at 4 CTAs/SM (vs 14 waves before).

#define N_ROWS 16384
#define D_COLS 2048
#define THREADS 256
#define RPC 8                      // rows per CTA
#define F4_PER_ROW (D_COLS / 4)    // 512

__global__ __launch_bounds__(THREADS, 4)
void attention_fusion_kernel(const float* __restrict__ x1,
                             const float* __restrict__ x2,
                             const float* __restrict__ w,
                             float* __restrict__ fused,
                             float* __restrict__ alpha) {
    const int tid  = threadIdx.x;
    const int lane = tid & 31;
    const int warp = tid >> 5;
    const int row0 = blockIdx.x * RPC;

    const float4* __restrict__ w4 = reinterpret_cast<const float4*>(w);
    // w cached in registers for all 8 rows
    const float4 w0 = w4[tid];
    const float4 w1 = w4[tid + THREADS];

    __shared__ float warp_sums[THREADS / 32];
    __shared__ float alpha1_sh;

    const float4* x1b = reinterpret_cast<const float4*>(x1) + (size_t)row0 * F4_PER_ROW;
    const float4* x2b = reinterpret_cast<const float4*>(x2) + (size_t)row0 * F4_PER_ROW;
    float4*       ob  = reinterpret_cast<float4*>(fused)    + (size_t)row0 * F4_PER_ROW;

    // Prime the pipeline: row 0 loads (streaming: evict-first)
    float4 a0 = __ldcs(&x1b[tid]);
    float4 a1 = __ldcs(&x1b[tid + THREADS]);
    float4 b0 = __ldcs(&x2b[tid]);
    float4 b1 = __ldcs(&x2b[tid + THREADS]);

    #pragma unroll
    for (int r = 0; r < RPC; r++) {
        // Issue next row's loads BEFORE this row's reduce/barrier stalls us
        float4 na0, na1, nb0, nb1;
        if (r + 1 < RPC) {
            const float4* nx1 = x1b + (size_t)(r + 1) * F4_PER_ROW;
            const float4* nx2 = x2b + (size_t)(r + 1) * F4_PER_ROW;
            na0 = __ldcs(&nx1[tid]);
            na1 = __ldcs(&nx1[tid + THREADS]);
            nb0 = __ldcs(&nx2[tid]);
            nb1 = __ldcs(&nx2[tid + THREADS]);
        }

        // Partial of d = dot(x1 - x2, w)
        float d = (a0.x - b0.x) * w0.x;
        d = fmaf(a0.y - b0.y, w0.y, d);
        d = fmaf(a0.z - b0.z, w0.z, d);
        d = fmaf(a0.w - b0.w, w0.w, d);
        d = fmaf(a1.x - b1.x, w1.x, d);
        d = fmaf(a1.y - b1.y, w1.y, d);
        d = fmaf(a1.z - b1.z, w1.z, d);
        d = fmaf(a1.w - b1.w, w1.w, d);

        // Warp reduce
        #pragma unroll
        for (int off = 16; off > 0; off >>= 1)
            d += __shfl_xor_sync(0xFFFFFFFFu, d, off);

        if (lane == 0) warp_sums[warp] = d;
        __syncthreads();

        if (warp == 0) {
            float v = (lane < THREADS / 32) ? warp_sums[lane] : 0.0f;
            #pragma unroll
            for (int off = 4; off > 0; off >>= 1)
                v += __shfl_xor_sync(0xFFFFFFFFu, v, off);
            if (lane == 0) {
                float a = 1.0f / (1.0f + expf(-v));
                alpha1_sh = a;
                const size_t arow = (size_t)(row0 + r) * 2;
                alpha[arow + 0] = a;
                alpha[arow + 1] = 1.0f - a;
            }
        }
        __syncthreads();

        const float al = alpha1_sh;

        float4 o0, o1;
        o0.x = fmaf(al, a0.x - b0.x, b0.x);   // al*a + (1-al)*b
        o0.y = fmaf(al, a0.y - b0.y, b0.y);
        o0.z = fmaf(al, a0.z - b0.z, b0.z);
        o0.w = fmaf(al, a0.w - b0.w, b0.w);
        o1.x = fmaf(al, a1.x - b1.x, b1.x);
        o1.y = fmaf(al, a1.y - b1.y, b1.y);
        o1.z = fmaf(al, a1.z - b1.z, b1.z);
        o1.w = fmaf(al, a1.w - b1.w, b1.w);

        float4* orow = ob + (size_t)r * F4_PER_ROW;
        __stcs(&orow[tid], o0);
        __stcs(&orow[tid + THREADS], o1);

        // Rotate double buffer (register renaming under full unroll)
        a0 = na0; a1 = na1; b0 = nb0; b1 = nb1;
    }
}

extern "C" void kernel_launch(void* const* d_in, const int* in_sizes, int n_in,
                              void* d_out, int out_size) {
    const float* x1 = (const float*)d_in[0];
    const float* x2 = (const float*)d_in[1];
    const float* w  = (const float*)d_in[2];
    float* out = (float*)d_out;

    float* fused = out;                           // [N, D]
    float* alpha = out + (size_t)N_ROWS * D_COLS; // [N, 2]

    attention_fusion_kernel<<<N_ROWS / RPC, THREADS>>>(x1, x2, w, fused, alpha);
}

// round 5
// speedup vs baseline: 1.0269x; 1.0269x over previous
#include <cuda_runtime.h>

// AttentionFusion: fused = sigmoid((x1-x2)@w) * x1 + (1-sigmoid) * x2
// N = 16384 rows, D = 2048 cols, fp32. Pure HBM streamer (402 MB min traffic).
//
// R4: back to R0 structure (1 row/CTA, 256 thr, 32 regs, occ 8/SM) — R3 showed
// occupancy beats per-warp MLP here. Changes vs R0:
//  - single __syncthreads: all threads redundantly sum the 8 warp partials and
//    compute sigmoid themselves (kills 2nd barrier + alpha broadcast chain)
//  - __ldcs/__stcs streaming hints on the touch-once tensors

#define N_ROWS 16384
#define D_COLS 2048
#define THREADS 256
#define NWARPS (THREADS / 32)

__global__ __launch_bounds__(THREADS, 8)
void attention_fusion_kernel(const float* __restrict__ x1,
                             const float* __restrict__ x2,
                             const float* __restrict__ w,
                             float* __restrict__ fused,
                             float* __restrict__ alpha) {
    const int row  = blockIdx.x;
    const int tid  = threadIdx.x;
    const int lane = tid & 31;
    const int warp = tid >> 5;

    const float4* __restrict__ x1r = reinterpret_cast<const float4*>(x1) + (size_t)row * (D_COLS / 4);
    const float4* __restrict__ x2r = reinterpret_cast<const float4*>(x2) + (size_t)row * (D_COLS / 4);
    const float4* __restrict__ w4  = reinterpret_cast<const float4*>(w);

    // Front-batched coalesced loads; x1/x2 streaming (touched once)
    float4 a0 = __ldcs(&x1r[tid]);
    float4 a1 = __ldcs(&x1r[tid + THREADS]);
    float4 b0 = __ldcs(&x2r[tid]);
    float4 b1 = __ldcs(&x2r[tid + THREADS]);
    float4 w0 = w4[tid];
    float4 w1 = w4[tid + THREADS];

    // Partial of d = dot(x1 - x2, w)
    float d = (a0.x - b0.x) * w0.x;
    d = fmaf(a0.y - b0.y, w0.y, d);
    d = fmaf(a0.z - b0.z, w0.z, d);
    d = fmaf(a0.w - b0.w, w0.w, d);
    d = fmaf(a1.x - b1.x, w1.x, d);
    d = fmaf(a1.y - b1.y, w1.y, d);
    d = fmaf(a1.z - b1.z, w1.z, d);
    d = fmaf(a1.w - b1.w, w1.w, d);

    // Warp reduce
    #pragma unroll
    for (int off = 16; off > 0; off >>= 1)
        d += __shfl_xor_sync(0xFFFFFFFFu, d, off);

    __shared__ float warp_sums[NWARPS];
    if (lane == 0) warp_sums[warp] = d;
    __syncthreads();   // the ONLY barrier

    // Every thread finishes the reduction itself (smem broadcast reads, cheap)
    float v = warp_sums[0];
    #pragma unroll
    for (int i = 1; i < NWARPS; i++) v += warp_sums[i];

    const float al = 1.0f / (1.0f + expf(-v));   // sigmoid(s1 - s2)

    if (tid == 0) {
        alpha[(size_t)row * 2 + 0] = al;
        alpha[(size_t)row * 2 + 1] = 1.0f - al;
    }

    float4* __restrict__ outr = reinterpret_cast<float4*>(fused) + (size_t)row * (D_COLS / 4);

    float4 o0, o1;
    o0.x = fmaf(al, a0.x - b0.x, b0.x);   // al*a + (1-al)*b = al*(a-b) + b
    o0.y = fmaf(al, a0.y - b0.y, b0.y);
    o0.z = fmaf(al, a0.z - b0.z, b0.z);
    o0.w = fmaf(al, a0.w - b0.w, b0.w);
    o1.x = fmaf(al, a1.x - b1.x, b1.x);
    o1.y = fmaf(al, a1.y - b1.y, b1.y);
    o1.z = fmaf(al, a1.z - b1.z, b1.z);
    o1.w = fmaf(al, a1.w - b1.w, b1.w);

    __stcs(&outr[tid], o0);
    __stcs(&outr[tid + THREADS], o1);
}

extern "C" void kernel_launch(void* const* d_in, const int* in_sizes, int n_in,
                              void* d_out, int out_size) {
    const float* x1 = (const float*)d_in[0];
    const float* x2 = (const float*)d_in[1];
    const float* w  = (const float*)d_in[2];
    float* out = (float*)d_out;

    float* fused = out;                           // [N, D]
    float* alpha = out + (size_t)N_ROWS * D_COLS; // [N, 2]

    attention_fusion_kernel<<<N_ROWS, THREADS>>>(x1, x2, w, fused, alpha);
}